// round 1
// baseline (speedup 1.0000x reference)
#include <cuda_runtime.h>
#include <math.h>

#define B    256
#define CTXD 512
#define DOF  6
#define WSZ  300
#define CATD 306
#define PG   256
#define PW   512
#define HG   256
#define HW   512
#define MS   20
#define NSTEPS 19

// ---------------- device scratch (no allocations allowed) ----------------
__device__ float g_Wt[(size_t)CATD * CTXD * PW];   // [j][i][o]  320MB
__device__ float g_Gt[(size_t)DOF  * CTXD * PG];   // [j][i][o]
__device__ float g_Aw[(size_t)B * CATD * PW];      // [b][j][o]  160MB
__device__ float g_Ag[(size_t)B * DOF  * PG];      // [b][j][o]
__device__ float g_xg[B * PG];
__device__ float g_x2[B * PG];
__device__ float g_yw[B * PW];
__device__ float g_y2[B * PW];
__device__ float g_cat[B * CATD];
__device__ float g_gh[2 * B * HG];
__device__ float g_gc[2 * B * HG];
__device__ float g_wh[2 * B * HW];
__device__ float g_wc[2 * B * HW];
__device__ float g_gatesG[B * 4 * HG];
__device__ float g_gatesW[B * 4 * HW];

__device__ __forceinline__ float sigf(float x) { return 1.f / (1.f + expf(-x)); }

// ---------------- transpose (o,i,j) -> (j,i,o) ----------------
__global__ void transpose_oij_jio(const float* __restrict__ in, float* __restrict__ out,
                                  int O, int I, int J) {
    __shared__ float tile[32][33];
    int i  = blockIdx.x;
    int o0 = blockIdx.y * 32;
    int j0 = blockIdx.z * 32;
    int tx = threadIdx.x, ty = threadIdx.y;
    int o = o0 + ty, j = j0 + tx;
    if (o < O && j < J)
        tile[ty][tx] = in[(size_t)o * I * J + (size_t)i * J + j];
    __syncthreads();
    int jo = j0 + ty, oo = o0 + tx;
    if (jo < J && oo < O)
        out[(size_t)jo * I * O + (size_t)i * O + oo] = tile[tx][ty];
}

// ---------------- precompute GEMM: C_z[m,n] = sum_k A[m,k] * B_z[k,n] ----------------
// BM=128, BN=64, BK=16, 256 threads, per-thread 8x4.  M%128==0, N%64==0, K%16==0.
__global__ void gemm_nn_batched(const float* __restrict__ A, int lda,
                                const float* __restrict__ Bm, size_t bStrideZ,
                                float* __restrict__ C, int ldc, int cStrideZ,
                                int N, int K) {
    __shared__ float As[16][129];
    __shared__ float Bs[16][65];
    int z = blockIdx.z;
    const float* Bz = Bm + (size_t)z * bStrideZ;
    float* Cz = C + (size_t)z * cStrideZ;
    int m0 = blockIdx.y * 128, n0 = blockIdx.x * 64;
    int t = threadIdx.x;
    int tx = t & 15, ty = t >> 4;
    float acc[8][4];
#pragma unroll
    for (int i = 0; i < 8; i++)
#pragma unroll
        for (int j = 0; j < 4; j++) acc[i][j] = 0.f;

    for (int k0 = 0; k0 < K; k0 += 16) {
#pragma unroll
        for (int i = 0; i < 8; i++) {
            int idx = t + i * 256;
            int r = idx >> 4, c = idx & 15;
            As[c][r] = A[(size_t)(m0 + r) * lda + k0 + c];
        }
#pragma unroll
        for (int i = 0; i < 4; i++) {
            int idx = t + i * 256;
            int r = idx >> 6, c = idx & 63;
            Bs[r][c] = Bz[(size_t)(k0 + r) * N + n0 + c];
        }
        __syncthreads();
#pragma unroll
        for (int kk = 0; kk < 16; kk++) {
            float a[8], bb[4];
#pragma unroll
            for (int i = 0; i < 8; i++) a[i] = As[kk][ty * 8 + i];
#pragma unroll
            for (int j = 0; j < 4; j++) bb[j] = Bs[kk][tx * 4 + j];
#pragma unroll
            for (int i = 0; i < 8; i++)
#pragma unroll
                for (int j = 0; j < 4; j++) acc[i][j] += a[i] * bb[j];
        }
        __syncthreads();
    }
#pragma unroll
    for (int i = 0; i < 8; i++)
#pragma unroll
        for (int j = 0; j < 4; j++)
            Cz[(size_t)(m0 + ty * 8 + i) * ldc + n0 + tx * 4 + j] = acc[i][j];
}

// ---------------- step GEMM: C[m,n] = act( sum_k A[m,k]W[n,k] + sum_k A2[m,k]W2[n,k] + bias ) ----
// BM=BN=64, BK=16, 256 threads, 4x4 per thread. M==256 assumed; N guarded; K%16==0.
__global__ void gemm_tn(const float* __restrict__ A, int lda, int K,
                        const float* __restrict__ W,
                        const float* __restrict__ A2, int lda2, int K2,
                        const float* __restrict__ W2,
                        const float* __restrict__ bias, const float* __restrict__ bias2,
                        float* __restrict__ C, int ldc,
                        float* __restrict__ C2, int ldc2,
                        int N, int act) {
    __shared__ float As[16][65];
    __shared__ float Ws[16][65];
    int m0 = blockIdx.y * 64, n0 = blockIdx.x * 64;
    int t = threadIdx.x;
    int tx = t & 15, ty = t >> 4;
    float acc[4][4];
#pragma unroll
    for (int i = 0; i < 4; i++)
#pragma unroll
        for (int j = 0; j < 4; j++) acc[i][j] = 0.f;

    for (int pass = 0; pass < 2; pass++) {
        const float* Ac = pass ? A2 : A;
        const float* Wc = pass ? W2 : W;
        const int Kc   = pass ? K2 : K;
        const int ldac = pass ? lda2 : lda;
        if (Kc <= 0) break;
        for (int k0 = 0; k0 < Kc; k0 += 16) {
#pragma unroll
            for (int i = 0; i < 4; i++) {
                int idx = t + i * 256;
                int r = idx >> 4, c = idx & 15;
                As[c][r] = Ac[(size_t)(m0 + r) * ldac + k0 + c];
                int nr = n0 + r;
                Ws[c][r] = (nr < N) ? Wc[(size_t)nr * Kc + k0 + c] : 0.f;
            }
            __syncthreads();
#pragma unroll
            for (int kk = 0; kk < 16; kk++) {
                float a[4], w[4];
#pragma unroll
                for (int i = 0; i < 4; i++) a[i] = As[kk][ty * 4 + i];
#pragma unroll
                for (int j = 0; j < 4; j++) w[j] = Ws[kk][tx * 4 + j];
#pragma unroll
                for (int i = 0; i < 4; i++)
#pragma unroll
                    for (int j = 0; j < 4; j++) acc[i][j] += a[i] * w[j];
            }
            __syncthreads();
        }
    }
#pragma unroll
    for (int i = 0; i < 4; i++) {
        int m = m0 + ty * 4 + i;
#pragma unroll
        for (int j = 0; j < 4; j++) {
            int n = n0 + tx * 4 + j;
            if (n < N) {
                float v = acc[i][j] + bias[n];
                if (bias2) v += bias2[n];
                if (act == 1) v = tanhf(v);
                C[(size_t)m * ldc + n] = v;
                if (C2) C2[(size_t)m * ldc2 + n] = v;
            }
        }
    }
}

// ---------------- bilinear apply: y = Aw . cat + bw_b ; x = Ag . pg + bg_b ----------------
__global__ void bilinear_apply(const float* __restrict__ bw_b, const float* __restrict__ bg_b) {
    int b = blockIdx.x;
    int part = blockIdx.y;
    int t = threadIdx.x;  // 256
    __shared__ float sc[CATD];
    for (int k = t; k < CATD; k += 256) sc[k] = g_cat[b * CATD + k];
    __syncthreads();
    if (part < 2) {
        int o = part * 256 + t;
        const float* a = g_Aw + (size_t)b * CATD * PW + o;
        float acc0 = bw_b[o];
        float acc1 = 0.f;
#pragma unroll 4
        for (int j = 0; j < CATD; j += 2) {
            acc0 += a[(size_t)j * PW] * sc[j];
            acc1 += a[(size_t)(j + 1) * PW] * sc[j + 1];
        }
        g_yw[b * PW + o] = acc0 + acc1;
    } else {
        int o = t;
        const float* a = g_Ag + (size_t)b * DOF * PG + o;
        float acc = bg_b[o];
#pragma unroll
        for (int j = 0; j < DOF; j++) acc += a[j * PG] * sc[j];
        g_xg[b * PG + o] = acc;
    }
}

// ---------------- LSTM pointwise ----------------
__global__ void lstm_point(const float* __restrict__ gates, float* __restrict__ h,
                           float* __restrict__ c, int H) {
    int idx = blockIdx.x * blockDim.x + threadIdx.x;  // B*H
    int b = idx / H, u = idx - b * H;
    const float* g = gates + (size_t)b * 4 * H;
    float ig = sigf(g[u]);
    float fg = sigf(g[H + u]);
    float gg = tanhf(g[2 * H + u]);
    float og = sigf(g[3 * H + u]);
    float cn = fg * c[idx] + ig * gg;
    c[idx] = cn;
    h[idx] = og * tanhf(cn);
}

// ---------------- init ----------------
__global__ void init_k(const float* __restrict__ goal0, const float* __restrict__ w0,
                       float* __restrict__ outGoals, float* __restrict__ outWs) {
    int idx = blockIdx.x * blockDim.x + threadIdx.x;  // up to 2*B*HW = 262144
    if (idx < 2 * B * HG) { g_gh[idx] = 0.f; g_gc[idx] = 0.f; }
    if (idx < 2 * B * HW) { g_wh[idx] = 0.f; g_wc[idx] = 0.f; }
    if (idx < B * DOF) {
        int b = idx / DOF, d = idx - b * DOF;
        float v = goal0[idx];
        g_cat[b * CATD + d] = v;
        outGoals[(size_t)b * MS * DOF + d] = v;
    }
    if (idx < B * WSZ) {
        int b = idx / WSZ, d = idx - b * WSZ;
        float v = w0[idx];
        g_cat[b * CATD + DOF + d] = v;
        outWs[(size_t)b * MS * WSZ + d] = v;
    }
}

// ---------------- host ----------------
extern "C" void kernel_launch(void* const* d_in, const int* in_sizes, int n_in,
                              void* d_out, int out_size) {
    const float* ctx    = (const float*)d_in[0];
    const float* goal0  = (const float*)d_in[1];
    const float* w0     = (const float*)d_in[2];
    const float* bg_W   = (const float*)d_in[3];
    const float* bg_b   = (const float*)d_in[4];
    const float* bw_W   = (const float*)d_in[5];
    const float* bw_b   = (const float*)d_in[6];
    const float* fcg_W  = (const float*)d_in[7];
    const float* fcg_b  = (const float*)d_in[8];
    const float* fcw_W  = (const float*)d_in[9];
    const float* fcw_b  = (const float*)d_in[10];
    const float* lg_Wih = (const float*)d_in[11];
    const float* lg_Whh = (const float*)d_in[12];
    const float* lg_bih = (const float*)d_in[13];
    const float* lg_bhh = (const float*)d_in[14];
    const float* lw_Wih = (const float*)d_in[15];
    const float* lw_Whh = (const float*)d_in[16];
    const float* lw_bih = (const float*)d_in[17];
    const float* lw_bhh = (const float*)d_in[18];
    const float* og_W   = (const float*)d_in[19];
    const float* og_b   = (const float*)d_in[20];
    const float* ow_W   = (const float*)d_in[21];
    const float* ow_b   = (const float*)d_in[22];

    float* out   = (float*)d_out;
    float* goals = out;                        // [B][MS][DOF]
    float* ws    = out + (size_t)B * MS * DOF; // [B][MS][WSZ]

    float *Wt, *Gt, *Aw, *Ag, *xg, *x2, *yw, *y2, *cat, *gh, *gc, *wh, *wc, *gatesG, *gatesW;
    cudaGetSymbolAddress((void**)&Wt, g_Wt);
    cudaGetSymbolAddress((void**)&Gt, g_Gt);
    cudaGetSymbolAddress((void**)&Aw, g_Aw);
    cudaGetSymbolAddress((void**)&Ag, g_Ag);
    cudaGetSymbolAddress((void**)&xg, g_xg);
    cudaGetSymbolAddress((void**)&x2, g_x2);
    cudaGetSymbolAddress((void**)&yw, g_yw);
    cudaGetSymbolAddress((void**)&y2, g_y2);
    cudaGetSymbolAddress((void**)&cat, g_cat);
    cudaGetSymbolAddress((void**)&gh, g_gh);
    cudaGetSymbolAddress((void**)&gc, g_gc);
    cudaGetSymbolAddress((void**)&wh, g_wh);
    cudaGetSymbolAddress((void**)&wc, g_wc);
    cudaGetSymbolAddress((void**)&gatesG, g_gatesG);
    cudaGetSymbolAddress((void**)&gatesW, g_gatesW);

    dim3 tblk(32, 32);
    // transpose bw_W (PW, CTX, CATD) -> Wt (CATD, CTX, PW)
    transpose_oij_jio<<<dim3(CTXD, PW / 32, (CATD + 31) / 32), tblk>>>(bw_W, Wt, PW, CTXD, CATD);
    // transpose bg_W (PG, CTX, DOF) -> Gt (DOF, CTX, PG)
    transpose_oij_jio<<<dim3(CTXD, PG / 32, 1), tblk>>>(bg_W, Gt, PG, CTXD, DOF);

    // Aw[b][j][o] = ctx @ Wt[j]
    gemm_nn_batched<<<dim3(PW / 64, B / 128, CATD), 256>>>(
        ctx, CTXD, Wt, (size_t)CTXD * PW, Aw, CATD * PW, PW, PW, CTXD);
    // Ag[b][j][o] = ctx @ Gt[j]
    gemm_nn_batched<<<dim3(PG / 64, B / 128, DOF), 256>>>(
        ctx, CTXD, Gt, (size_t)CTXD * PG, Ag, DOF * PG, PG, PG, CTXD);

    init_k<<<(2 * B * HW) / 256, 256>>>(goal0, w0, goals, ws);

    for (int s = 0; s < NSTEPS; s++) {
        // bilinear: y = Aw.cat + bw_b ; x = Ag.pg + bg_b
        bilinear_apply<<<dim3(B, 3), 256>>>(bw_b, bg_b);

        // fc + tanh
        gemm_tn<<<dim3(PG / 64, 4), 256>>>(xg, PG, PG, fcg_W,
                                           nullptr, 0, 0, nullptr,
                                           fcg_b, nullptr, x2, PG, nullptr, 0, PG, 1);
        gemm_tn<<<dim3(PW / 64, 4), 256>>>(yw, PW, PW, fcw_W,
                                           nullptr, 0, 0, nullptr,
                                           fcw_b, nullptr, y2, PW, nullptr, 0, PW, 1);

        // LSTM g, layer 0
        gemm_tn<<<dim3(4 * HG / 64, 4), 256>>>(x2, PG, PG, lg_Wih,
                                               gh, HG, HG, lg_Whh,
                                               lg_bih, lg_bhh, gatesG, 4 * HG,
                                               nullptr, 0, 4 * HG, 0);
        lstm_point<<<(B * HG) / 256, 256>>>(gatesG, gh, gc, HG);
        // LSTM g, layer 1 (input = new layer-0 h)
        gemm_tn<<<dim3(4 * HG / 64, 4), 256>>>(gh, HG, HG, lg_Wih + (size_t)4 * HG * PG,
                                               gh + B * HG, HG, HG, lg_Whh + (size_t)4 * HG * HG,
                                               lg_bih + 4 * HG, lg_bhh + 4 * HG, gatesG, 4 * HG,
                                               nullptr, 0, 4 * HG, 0);
        lstm_point<<<(B * HG) / 256, 256>>>(gatesG, gh + B * HG, gc + B * HG, HG);

        // LSTM w, layer 0
        gemm_tn<<<dim3(4 * HW / 64, 4), 256>>>(y2, PW, PW, lw_Wih,
                                               wh, HW, HW, lw_Whh,
                                               lw_bih, lw_bhh, gatesW, 4 * HW,
                                               nullptr, 0, 4 * HW, 0);
        lstm_point<<<(B * HW) / 256, 256>>>(gatesW, wh, wc, HW);
        // LSTM w, layer 1
        gemm_tn<<<dim3(4 * HW / 64, 4), 256>>>(wh, HW, HW, lw_Wih + (size_t)4 * HW * PW,
                                               wh + B * HW, HW, HW, lw_Whh + (size_t)4 * HW * HW,
                                               lw_bih + 4 * HW, lw_bhh + 4 * HW, gatesW, 4 * HW,
                                               nullptr, 0, 4 * HW, 0);
        lstm_point<<<(B * HW) / 256, 256>>>(gatesW, wh + B * HW, wc + B * HW, HW);

        // outputs: ng -> goals[:, s+1, :] and cat[:, 0:6]; nw -> ws[:, s+1, :] and cat[:, 6:306]
        gemm_tn<<<dim3(1, 4), 256>>>(gh + B * HG, HG, HG, og_W,
                                     nullptr, 0, 0, nullptr,
                                     og_b, nullptr,
                                     goals + (size_t)(s + 1) * DOF, MS * DOF,
                                     cat, CATD, DOF, 0);
        gemm_tn<<<dim3((WSZ + 63) / 64, 4), 256>>>(wh + B * HW, HW, HW, ow_W,
                                                   nullptr, 0, 0, nullptr,
                                                   ow_b, nullptr,
                                                   ws + (size_t)(s + 1) * WSZ, MS * WSZ,
                                                   cat + DOF, CATD, WSZ, 0);
    }
    (void)in_sizes; (void)n_in; (void)out_size;
}